// round 8
// baseline (speedup 1.0000x reference)
#include <cuda_runtime.h>
#include <cuda_bf16.h>
#include <cstdint>
#include <cstring>

#define N_NODES 100000
#define N_EDGES 1600000
#define IN_DIM  512
#define HID_DIM 64
#define NSB ((N_NODES + 1023) / 1024)   // 98 scan blocks

// fused-launch geometry
#define HB 3125                          // hist/reorder blocks (512 edges each)
#define GB1 391                          // gemm1 blocks in fusedA (rows 0..50047)
#define GB2 391                          // gemm1 blocks in fusedB (rows 50048..)
#define ROWS_A (GB1 * 128)

// ---------------- scratch (static device globals: allocation-free) ----------
__device__ int   g_idx64;
__device__ float g_deg[N_NODES];
__device__ float g_dinv[N_NODES];
__device__ int   g_cnt[N_NODES];
__device__ int   g_rs[N_NODES + 1];
__device__ int   g_cur[N_NODES];
__device__ int   g_bsum[NSB];
__device__ int   g_boff[NSB];
__device__ int   g_src[N_EDGES];
__device__ float g_w[N_EDGES];
__device__ float g_h[(size_t)N_NODES * HID_DIM];   // GEMM output (both layers)
__device__ float g_h2[(size_t)N_NODES * HID_DIM];  // layer-1 agg output
// bf16 hi/lo split of W, stored [n][k] (B operand)
__device__ __nv_bfloat16 g_b1hi[64 * IN_DIM];
__device__ __nv_bfloat16 g_b1lo[64 * IN_DIM];
__device__ __nv_bfloat16 g_b2hi[64 * HID_DIM];
__device__ __nv_bfloat16 g_b2lo[64 * HID_DIM];

// ---------------- helpers -----------------------------------------------------
__device__ __forceinline__ uint32_t pkbf(__nv_bfloat16 a, __nv_bfloat16 b) {
    __nv_bfloat162 t = __halves2bfloat162(a, b);
    uint32_t u; memcpy(&u, &t, 4); return u;
}
__device__ __forceinline__ void mma_bf16(float* c, const uint32_t* a,
                                         uint32_t b0, uint32_t b1) {
    asm("mma.sync.aligned.m16n8k16.row.col.f32.bf16.bf16.f32 "
        "{%0,%1,%2,%3},{%4,%5,%6,%7},{%8,%9},{%0,%1,%2,%3};"
        : "+f"(c[0]), "+f"(c[1]), "+f"(c[2]), "+f"(c[3])
        : "r"(a[0]), "r"(a[1]), "r"(a[2]), "r"(a[3]), "r"(b0), "r"(b1));
}
__device__ __forceinline__ int load_idx(const void* ei, long long pos) {
    if (g_idx64) return (int)((const long long*)ei)[pos];
    return ((const int*)ei)[pos];
}

// ---------------- bf16 mma GEMM body (device function) -----------------------
// 128 threads (4 warps), tile 128 x 64 at rowBase. K chunked by 32.
// 3-pass bf16 hi/lo split, fp32 accum. SMEM rows padded to 20 words.
template <int K, bool FROM_G_H2>
__device__ void gemm_body(const float* __restrict__ Xext, int rowBase) {
    __shared__ uint32_t ash[128][20];
    __shared__ uint32_t asl[128][20];
    __shared__ uint32_t bsh[64][20];
    __shared__ uint32_t bsl[64][20];

    const float* X = FROM_G_H2 ? (const float*)g_h2 : Xext;
    const __nv_bfloat16* Bhi = (K == IN_DIM) ? g_b1hi : g_b2hi;
    const __nv_bfloat16* Blo = (K == IN_DIM) ? g_b1lo : g_b2lo;

    const int M = N_NODES;
    int t = threadIdx.x, wid = t >> 5, lane = t & 31;
    int g = lane >> 2, tig = lane & 3;

    float acc[2][8][4] = {};

    for (int ch = 0; ch < K / 32; ch++) {
        int k0 = ch * 32;
        __syncthreads();
#pragma unroll
        for (int it = 0; it < 8; it++) {
            int id = t + it * 128;
            int row = id >> 3, q = id & 7;
            int gr = rowBase + row;
            float4 v = make_float4(0.f, 0.f, 0.f, 0.f);
            if (gr < M) v = *(const float4*)(X + (size_t)gr * K + k0 + q * 4);
            __nv_bfloat16 hx = __float2bfloat16(v.x), hy = __float2bfloat16(v.y);
            __nv_bfloat16 hz = __float2bfloat16(v.z), hw = __float2bfloat16(v.w);
            ash[row][q * 2]     = pkbf(hx, hy);
            ash[row][q * 2 + 1] = pkbf(hz, hw);
            asl[row][q * 2]     = pkbf(__float2bfloat16(v.x - __bfloat162float(hx)),
                                       __float2bfloat16(v.y - __bfloat162float(hy)));
            asl[row][q * 2 + 1] = pkbf(__float2bfloat16(v.z - __bfloat162float(hz)),
                                       __float2bfloat16(v.w - __bfloat162float(hw)));
        }
#pragma unroll
        for (int it = 0; it < 2; it++) {
            int id = t + it * 128;
            int n = id >> 2, u = id & 3;
            *(uint4*)&bsh[n][u * 4] = *(const uint4*)(Bhi + (size_t)n * K + k0 + u * 8);
            *(uint4*)&bsl[n][u * 4] = *(const uint4*)(Blo + (size_t)n * K + k0 + u * 8);
        }
        __syncthreads();

#pragma unroll
        for (int ks = 0; ks < 2; ks++) {
            int w0 = tig + 8 * ks;
            int w1 = tig + 4 + 8 * ks;
            uint32_t ah[2][4], al[2][4];
#pragma unroll
            for (int mt = 0; mt < 2; mt++) {
                int r = wid * 32 + mt * 16 + g;
                ah[mt][0] = ash[r][w0];  ah[mt][1] = ash[r + 8][w0];
                ah[mt][2] = ash[r][w1];  ah[mt][3] = ash[r + 8][w1];
                al[mt][0] = asl[r][w0];  al[mt][1] = asl[r + 8][w0];
                al[mt][2] = asl[r][w1];  al[mt][3] = asl[r + 8][w1];
            }
#pragma unroll
            for (int nt = 0; nt < 8; nt++) {
                int n = nt * 8 + g;
                uint32_t bh0 = bsh[n][w0], bh1 = bsh[n][w1];
                uint32_t bl0 = bsl[n][w0], bl1 = bsl[n][w1];
#pragma unroll
                for (int mt = 0; mt < 2; mt++) {
                    mma_bf16(acc[mt][nt], ah[mt], bh0, bh1);
                    mma_bf16(acc[mt][nt], ah[mt], bl0, bl1);
                    mma_bf16(acc[mt][nt], al[mt], bh0, bh1);
                }
            }
        }
    }
#pragma unroll
    for (int mt = 0; mt < 2; mt++) {
        int r0g = rowBase + wid * 32 + mt * 16 + g;
#pragma unroll
        for (int nt = 0; nt < 8; nt++) {
            int col = nt * 8 + tig * 2;
            if (r0g < M)
                *(float2*)(g_h + (size_t)r0g * 64 + col) =
                    make_float2(acc[mt][nt][0], acc[mt][nt][1]);
            if (r0g + 8 < M)
                *(float2*)(g_h + (size_t)(r0g + 8) * 64 + col) =
                    make_float2(acc[mt][nt][2], acc[mt][nt][3]);
        }
    }
}

// ---------------- edge-pass bodies (128 threads, 512 edges per block) --------
__device__ void hist_body(int bid, const void* __restrict__ ei,
                          const float* __restrict__ ew) {
    int base = bid * 512 + threadIdx.x;
#pragma unroll
    for (int r = 0; r < 4; r++) {
        int e = base + r * 128;
        if (e < N_EDGES) {
            int d = load_idx(ei, (long long)N_EDGES + e);
            if ((unsigned)d < (unsigned)N_NODES) {
                atomicAdd(&g_deg[d], ew[e]);
                atomicAdd(&g_cnt[d], 1);
            }
        }
    }
}

__device__ void reorder_body(int bid, const void* __restrict__ ei,
                             const float* __restrict__ ew) {
    int base = bid * 512 + threadIdx.x;
#pragma unroll
    for (int r = 0; r < 4; r++) {
        int e = base + r * 128;
        if (e < N_EDGES) {
            int s = load_idx(ei, e);
            int d = load_idx(ei, (long long)N_EDGES + e);
            if ((unsigned)d < (unsigned)N_NODES) {
                int p = atomicAdd(&g_cur[d], 1);
                if ((unsigned)s < (unsigned)N_NODES) {
                    g_src[p] = s;
                    g_w[p]   = g_dinv[s] * ew[e] * g_dinv[d];
                } else {
                    g_src[p] = 0;
                    g_w[p]   = 0.0f;
                }
            }
        }
    }
}

// ---------------- fused launches ---------------------------------------------
// fusedA: blocks [0,HB) = deg hist, [HB,HB+GB1) = gemm1 rows [0, ROWS_A)
__global__ void __launch_bounds__(128) fusedA_kernel(
    const void* __restrict__ ei, const float* __restrict__ ew,
    const float* __restrict__ x) {
    if (blockIdx.x < HB) hist_body(blockIdx.x, ei, ew);
    else gemm_body<IN_DIM, false>(x, (int)(blockIdx.x - HB) * 128);
}

// fusedB: blocks [0,HB) = reorder, [HB,HB+GB2) = gemm1 rows [ROWS_A, M)
__global__ void __launch_bounds__(128) fusedB_kernel(
    const void* __restrict__ ei, const float* __restrict__ ew,
    const float* __restrict__ x) {
    if (blockIdx.x < HB) reorder_body(blockIdx.x, ei, ew);
    else gemm_body<IN_DIM, false>(x, ROWS_A + (int)(blockIdx.x - HB) * 128);
}

// layer-2 GEMM (standalone)
__global__ void __launch_bounds__(128) gemm2_kernel() {
    gemm_body<HID_DIM, true>(nullptr, (int)blockIdx.x * 128);
}

// ---------------- init: deg/cnt + dtype detect + W split ---------------------
__global__ void init_kernel(const int* __restrict__ ei32,
                            const float* __restrict__ W1,
                            const float* __restrict__ W2) {
    int i = blockIdx.x * blockDim.x + threadIdx.x;
    if (i < N_NODES) { g_deg[i] = 1.0f; g_cnt[i] = 0; }  // self-loop weight 1
    if (blockIdx.x == 0 && threadIdx.x < 32) {
        int nz = 0;
#pragma unroll
        for (int j = 0; j < 4; j++) nz |= ei32[1 + 2 * (threadIdx.x * 4 + j)];
        unsigned b = __ballot_sync(0xffffffffu, nz != 0);
        if (threadIdx.x == 0) g_idx64 = (b == 0u) ? 1 : 0;
    }
    if (i < IN_DIM * 64) {
        int k = i / 64, n = i % 64;
        float w = W1[i];
        __nv_bfloat16 h = __float2bfloat16(w);
        g_b1hi[n * IN_DIM + k] = h;
        g_b1lo[n * IN_DIM + k] = __float2bfloat16(w - __bfloat162float(h));
    }
    if (i < HID_DIM * 64) {
        int k = i / 64, n = i % 64;
        float w = W2[i];
        __nv_bfloat16 h = __float2bfloat16(w);
        g_b2hi[n * HID_DIM + k] = h;
        g_b2lo[n * HID_DIM + k] = __float2bfloat16(w - __bfloat162float(h));
    }
}

// ---------------- scans -------------------------------------------------------
__global__ void scan1_kernel() {
    __shared__ int ws[32];
    int b = blockIdx.x, tid = threadIdx.x, lane = tid & 31, wid = tid >> 5;
    int i = b * 1024 + tid;
    if (i < N_NODES) {
        float d = g_deg[i];
        g_dinv[i] = (d > 0.0f) ? rsqrtf(d) : 0.0f;
    }
    int v = (i < N_NODES) ? g_cnt[i] : 0;
    int x = v;
#pragma unroll
    for (int off = 1; off < 32; off <<= 1) {
        int y = __shfl_up_sync(0xffffffffu, x, off);
        if (lane >= off) x += y;
    }
    if (lane == 31) ws[wid] = x;
    __syncthreads();
    if (wid == 0) {
        int s = ws[lane];
#pragma unroll
        for (int off = 1; off < 32; off <<= 1) {
            int y = __shfl_up_sync(0xffffffffu, s, off);
            if (lane >= off) s += y;
        }
        ws[lane] = s;
    }
    __syncthreads();
    int incl = x + (wid > 0 ? ws[wid - 1] : 0);
    if (i < N_NODES) g_rs[i] = incl - v;
    if (tid == 1023) g_bsum[b] = incl;
}

__global__ void scan2_kernel() {
    __shared__ int ws[4];
    int tid = threadIdx.x, lane = tid & 31, wid = tid >> 5;
    int v = (tid < NSB) ? g_bsum[tid] : 0;
    int x = v;
#pragma unroll
    for (int off = 1; off < 32; off <<= 1) {
        int y = __shfl_up_sync(0xffffffffu, x, off);
        if (lane >= off) x += y;
    }
    if (lane == 31) ws[wid] = x;
    __syncthreads();
    if (tid == 0) {
        int a = 0;
        for (int j = 0; j < 4; j++) { int t = ws[j]; ws[j] = a; a += t; }
    }
    __syncthreads();
    int excl = x - v + ws[wid];
    if (tid < NSB) g_boff[tid] = excl;
    if (tid == NSB - 1) g_rs[N_NODES] = excl + v;
}

__global__ void scan3_kernel() {
    int i = blockIdx.x * 1024 + threadIdx.x;
    if (i < N_NODES) {
        int r = g_rs[i] + g_boff[blockIdx.x];
        g_rs[i] = r;
        g_cur[i] = r;
    }
}

// ---------------- aggregation: warp per node, CSR gather, no atomics --------
template <bool RELU>
__global__ void __launch_bounds__(256) agg_kernel(
    const float* __restrict__ bias, float2* __restrict__ outp) {
    const float2* H = (const float2*)g_h;
    float2* out = RELU ? (float2*)g_h2 : outp;

    int gw   = (blockIdx.x * blockDim.x + threadIdx.x) >> 5;
    int lane = threadIdx.x & 31;
    if (gw >= N_NODES) return;
    int node = gw;

    float di = g_dinv[node];
    float sn = di * di;
    float2 hv = H[(size_t)node * 32 + lane];
    float ax = sn * hv.x, ay = sn * hv.y;

    int b = g_rs[node], en = g_rs[node + 1];
    for (int i = b; i < en; i += 32) {
        int rem = en - i;
        int src = 0; float w = 0.f;
        if (lane < rem) { src = g_src[i + lane]; w = g_w[i + lane]; }
        int m = rem < 32 ? rem : 32;
        int j = 0;
        for (; j + 4 <= m; j += 4) {
            int   s0 = __shfl_sync(0xffffffffu, src, j);
            int   s1 = __shfl_sync(0xffffffffu, src, j + 1);
            int   s2 = __shfl_sync(0xffffffffu, src, j + 2);
            int   s3 = __shfl_sync(0xffffffffu, src, j + 3);
            float w0 = __shfl_sync(0xffffffffu, w, j);
            float w1 = __shfl_sync(0xffffffffu, w, j + 1);
            float w2 = __shfl_sync(0xffffffffu, w, j + 2);
            float w3 = __shfl_sync(0xffffffffu, w, j + 3);
            float2 x0 = H[(size_t)s0 * 32 + lane];
            float2 x1 = H[(size_t)s1 * 32 + lane];
            float2 x2 = H[(size_t)s2 * 32 + lane];
            float2 x3 = H[(size_t)s3 * 32 + lane];
            ax += w0 * x0.x; ay += w0 * x0.y;
            ax += w1 * x1.x; ay += w1 * x1.y;
            ax += w2 * x2.x; ay += w2 * x2.y;
            ax += w3 * x3.x; ay += w3 * x3.y;
        }
        for (; j < m; j++) {
            int   s0 = __shfl_sync(0xffffffffu, src, j);
            float w0 = __shfl_sync(0xffffffffu, w, j);
            float2 x0 = H[(size_t)s0 * 32 + lane];
            ax += w0 * x0.x; ay += w0 * x0.y;
        }
    }
    float2 bb = ((const float2*)bias)[lane];
    ax += bb.x; ay += bb.y;
    if (RELU) { ax = fmaxf(ax, 0.f); ay = fmaxf(ay, 0.f); }
    out[(size_t)node * 32 + lane] = make_float2(ax, ay);
}

// ---------------- launch -----------------------------------------------------
extern "C" void kernel_launch(void* const* d_in, const int* in_sizes, int n_in,
                              void* d_out, int out_size) {
    const float* x   = (const float*)d_in[0];
    const void*  ei  = d_in[1];
    const float* ew  = (const float*)d_in[2];
    const float* W1  = (const float*)d_in[3];
    const float* b1  = (const float*)d_in[4];
    const float* W2  = (const float*)d_in[5];
    const float* b2  = (const float*)d_in[6];
    float*       out = (float*)d_out;

    const int TPB = 256;
    int nBlocksN = (N_NODES + TPB - 1) / TPB;
    int aggBlocks = (N_NODES + 7) / 8;
    int gemm2Blocks = (N_NODES + 127) / 128;

    init_kernel<<<nBlocksN, TPB>>>((const int*)ei, W1, W2);
    fusedA_kernel<<<HB + GB1, 128>>>(ei, ew, x);      // hist || gemm1 (rows 0..50047)
    scan1_kernel<<<NSB, 1024>>>();
    scan2_kernel<<<1, 128>>>();
    scan3_kernel<<<NSB, 1024>>>();
    fusedB_kernel<<<HB + GB2, 128>>>(ei, ew, x);      // reorder || gemm1 (rows 50048..)

    agg_kernel<true><<<aggBlocks, TPB>>>(b1, nullptr);
    gemm2_kernel<<<gemm2Blocks, 128>>>();
    agg_kernel<false><<<aggBlocks, TPB>>>(b2, (float2*)out);
}

// round 9
// speedup vs baseline: 1.0352x; 1.0352x over previous
#include <cuda_runtime.h>
#include <cuda_bf16.h>
#include <cstdint>
#include <cstring>

#define N_NODES 100000
#define N_EDGES 1600000
#define IN_DIM  512
#define HID_DIM 64
#define NSB ((N_NODES + 1023) / 1024)   // 98 scan blocks

// ---------------- scratch (static device globals: allocation-free) ----------
__device__ int   g_idx64;
__device__ float g_deg[N_NODES];
__device__ float g_dinv[N_NODES];
__device__ int   g_cnt[N_NODES];
__device__ int   g_rs[N_NODES + 1];
__device__ int   g_cur[N_NODES];
__device__ int   g_bsum[NSB];
__device__ int   g_boff[NSB];
__device__ int   g_src[N_EDGES];
__device__ float g_w[N_EDGES];
__device__ float g_h[(size_t)N_NODES * HID_DIM];   // gemm1 output
__device__ float g_h2[(size_t)N_NODES * HID_DIM];  // fused agg1+gemm2 output
// bf16 hi/lo split of W, stored [n][k] (B operand)
__device__ __nv_bfloat16 g_b1hi[64 * IN_DIM];
__device__ __nv_bfloat16 g_b1lo[64 * IN_DIM];
__device__ __nv_bfloat16 g_b2hi[64 * HID_DIM];
__device__ __nv_bfloat16 g_b2lo[64 * HID_DIM];

// ---------------- helpers -----------------------------------------------------
__device__ __forceinline__ uint32_t pkbf(__nv_bfloat16 a, __nv_bfloat16 b) {
    __nv_bfloat162 t = __halves2bfloat162(a, b);
    uint32_t u; memcpy(&u, &t, 4); return u;
}
__device__ __forceinline__ uint32_t split_pack(float x, float y, uint32_t& lo) {
    __nv_bfloat16 hx = __float2bfloat16(x), hy = __float2bfloat16(y);
    lo = pkbf(__float2bfloat16(x - __bfloat162float(hx)),
              __float2bfloat16(y - __bfloat162float(hy)));
    return pkbf(hx, hy);
}
__device__ __forceinline__ void mma_bf16(float* c, const uint32_t* a,
                                         uint32_t b0, uint32_t b1) {
    asm("mma.sync.aligned.m16n8k16.row.col.f32.bf16.bf16.f32 "
        "{%0,%1,%2,%3},{%4,%5,%6,%7},{%8,%9},{%0,%1,%2,%3};"
        : "+f"(c[0]), "+f"(c[1]), "+f"(c[2]), "+f"(c[3])
        : "r"(a[0]), "r"(a[1]), "r"(a[2]), "r"(a[3]), "r"(b0), "r"(b1));
}
__device__ __forceinline__ int load_idx(const void* ei, long long pos) {
    if (g_idx64) return (int)((const long long*)ei)[pos];
    return ((const int*)ei)[pos];
}

// warp-collective: aggregate one node's 2 columns (2*lane, 2*lane+1) from H
__device__ __forceinline__ float2 agg_node(const float2* __restrict__ H,
                                           int node, int lane) {
    float di = g_dinv[node];
    float sn = di * di;
    float2 hv = H[(size_t)node * 32 + lane];
    float ax = sn * hv.x, ay = sn * hv.y;

    int b = g_rs[node], en = g_rs[node + 1];
    for (int i = b; i < en; i += 32) {
        int rem = en - i;
        int src = 0; float w = 0.f;
        if (lane < rem) { src = g_src[i + lane]; w = g_w[i + lane]; }
        int m = rem < 32 ? rem : 32;
        int j = 0;
        for (; j + 4 <= m; j += 4) {
            int   s0 = __shfl_sync(0xffffffffu, src, j);
            int   s1 = __shfl_sync(0xffffffffu, src, j + 1);
            int   s2 = __shfl_sync(0xffffffffu, src, j + 2);
            int   s3 = __shfl_sync(0xffffffffu, src, j + 3);
            float w0 = __shfl_sync(0xffffffffu, w, j);
            float w1 = __shfl_sync(0xffffffffu, w, j + 1);
            float w2 = __shfl_sync(0xffffffffu, w, j + 2);
            float w3 = __shfl_sync(0xffffffffu, w, j + 3);
            float2 x0 = H[(size_t)s0 * 32 + lane];
            float2 x1 = H[(size_t)s1 * 32 + lane];
            float2 x2 = H[(size_t)s2 * 32 + lane];
            float2 x3 = H[(size_t)s3 * 32 + lane];
            ax += w0 * x0.x; ay += w0 * x0.y;
            ax += w1 * x1.x; ay += w1 * x1.y;
            ax += w2 * x2.x; ay += w2 * x2.y;
            ax += w3 * x3.x; ay += w3 * x3.y;
        }
        for (; j < m; j++) {
            int   s0 = __shfl_sync(0xffffffffu, src, j);
            float w0 = __shfl_sync(0xffffffffu, w, j);
            float2 x0 = H[(size_t)s0 * 32 + lane];
            ax += w0 * x0.x; ay += w0 * x0.y;
        }
    }
    return make_float2(ax, ay);
}

// ---------------- init: deg/cnt + dtype detect + W split ---------------------
__global__ void init_kernel(const int* __restrict__ ei32,
                            const float* __restrict__ W1,
                            const float* __restrict__ W2) {
    int i = blockIdx.x * blockDim.x + threadIdx.x;
    if (i < N_NODES) { g_deg[i] = 1.0f; g_cnt[i] = 0; }  // self-loop weight 1
    if (blockIdx.x == 0 && threadIdx.x < 32) {
        int nz = 0;
#pragma unroll
        for (int j = 0; j < 4; j++) nz |= ei32[1 + 2 * (threadIdx.x * 4 + j)];
        unsigned b = __ballot_sync(0xffffffffu, nz != 0);
        if (threadIdx.x == 0) g_idx64 = (b == 0u) ? 1 : 0;
    }
    if (i < IN_DIM * 64) {
        int k = i / 64, n = i % 64;
        float w = W1[i];
        __nv_bfloat16 h = __float2bfloat16(w);
        g_b1hi[n * IN_DIM + k] = h;
        g_b1lo[n * IN_DIM + k] = __float2bfloat16(w - __bfloat162float(h));
    }
    if (i < HID_DIM * 64) {
        int k = i / 64, n = i % 64;
        float w = W2[i];
        __nv_bfloat16 h = __float2bfloat16(w);
        g_b2hi[n * HID_DIM + k] = h;
        g_b2lo[n * HID_DIM + k] = __float2bfloat16(w - __bfloat162float(h));
    }
}

__global__ void deg_hist_kernel(const void* __restrict__ ei,
                                const float* __restrict__ ew) {
    int e = blockIdx.x * blockDim.x + threadIdx.x;
    if (e >= N_EDGES) return;
    int d = load_idx(ei, (long long)N_EDGES + e);
    if ((unsigned)d < (unsigned)N_NODES) {
        atomicAdd(&g_deg[d], ew[e]);
        atomicAdd(&g_cnt[d], 1);
    }
}

// ---------------- scans -------------------------------------------------------
__global__ void scan1_kernel() {
    __shared__ int ws[32];
    int b = blockIdx.x, tid = threadIdx.x, lane = tid & 31, wid = tid >> 5;
    int i = b * 1024 + tid;
    if (i < N_NODES) {
        float d = g_deg[i];
        g_dinv[i] = (d > 0.0f) ? rsqrtf(d) : 0.0f;
    }
    int v = (i < N_NODES) ? g_cnt[i] : 0;
    int x = v;
#pragma unroll
    for (int off = 1; off < 32; off <<= 1) {
        int y = __shfl_up_sync(0xffffffffu, x, off);
        if (lane >= off) x += y;
    }
    if (lane == 31) ws[wid] = x;
    __syncthreads();
    if (wid == 0) {
        int s = ws[lane];
#pragma unroll
        for (int off = 1; off < 32; off <<= 1) {
            int y = __shfl_up_sync(0xffffffffu, s, off);
            if (lane >= off) s += y;
        }
        ws[lane] = s;
    }
    __syncthreads();
    int incl = x + (wid > 0 ? ws[wid - 1] : 0);
    if (i < N_NODES) g_rs[i] = incl - v;
    if (tid == 1023) g_bsum[b] = incl;
}

__global__ void scan2_kernel() {
    __shared__ int ws[4];
    int tid = threadIdx.x, lane = tid & 31, wid = tid >> 5;
    int v = (tid < NSB) ? g_bsum[tid] : 0;
    int x = v;
#pragma unroll
    for (int off = 1; off < 32; off <<= 1) {
        int y = __shfl_up_sync(0xffffffffu, x, off);
        if (lane >= off) x += y;
    }
    if (lane == 31) ws[wid] = x;
    __syncthreads();
    if (tid == 0) {
        int a = 0;
        for (int j = 0; j < 4; j++) { int t = ws[j]; ws[j] = a; a += t; }
    }
    __syncthreads();
    int excl = x - v + ws[wid];
    if (tid < NSB) g_boff[tid] = excl;
    if (tid == NSB - 1) g_rs[N_NODES] = excl + v;
}

__global__ void scan3_kernel() {
    int i = blockIdx.x * 1024 + threadIdx.x;
    if (i < N_NODES) {
        int r = g_rs[i] + g_boff[blockIdx.x];
        g_rs[i] = r;
        g_cur[i] = r;
    }
}

__global__ void reorder_kernel(const void* __restrict__ ei,
                               const float* __restrict__ ew) {
    int e = blockIdx.x * blockDim.x + threadIdx.x;
    if (e >= N_EDGES) return;
    int s = load_idx(ei, e);
    int d = load_idx(ei, (long long)N_EDGES + e);
    if ((unsigned)d >= (unsigned)N_NODES) return;
    int p = atomicAdd(&g_cur[d], 1);
    if ((unsigned)s < (unsigned)N_NODES) {
        g_src[p] = s;
        g_w[p]   = g_dinv[s] * ew[e] * g_dinv[d];
    } else {
        g_src[p] = 0;
        g_w[p]   = 0.0f;
    }
}

// ---------------- gemm1: g_h[M,64] = X[M,512] @ W1, bf16 3-pass --------------
__global__ void __launch_bounds__(128) gemm1_kernel(const float* __restrict__ X) {
    __shared__ uint32_t ash[128][20];
    __shared__ uint32_t asl[128][20];
    __shared__ uint32_t bsh[64][20];
    __shared__ uint32_t bsl[64][20];

    const int K = IN_DIM, M = N_NODES;
    int t = threadIdx.x, wid = t >> 5, lane = t & 31;
    int g = lane >> 2, tig = lane & 3;
    int rowBase = blockIdx.x * 128;

    float acc[2][8][4] = {};

    for (int ch = 0; ch < K / 32; ch++) {
        int k0 = ch * 32;
        __syncthreads();
#pragma unroll
        for (int it = 0; it < 8; it++) {
            int id = t + it * 128;
            int row = id >> 3, q = id & 7;
            int gr = rowBase + row;
            float4 v = make_float4(0.f, 0.f, 0.f, 0.f);
            if (gr < M) v = *(const float4*)(X + (size_t)gr * K + k0 + q * 4);
            uint32_t l0, l1;
            uint32_t h0 = split_pack(v.x, v.y, l0);
            uint32_t h1 = split_pack(v.z, v.w, l1);
            ash[row][q * 2] = h0; ash[row][q * 2 + 1] = h1;
            asl[row][q * 2] = l0; asl[row][q * 2 + 1] = l1;
        }
#pragma unroll
        for (int it = 0; it < 2; it++) {
            int id = t + it * 128;
            int n = id >> 2, u = id & 3;
            *(uint4*)&bsh[n][u * 4] = *(const uint4*)(g_b1hi + (size_t)n * K + k0 + u * 8);
            *(uint4*)&bsl[n][u * 4] = *(const uint4*)(g_b1lo + (size_t)n * K + k0 + u * 8);
        }
        __syncthreads();

#pragma unroll
        for (int ks = 0; ks < 2; ks++) {
            int w0 = tig + 8 * ks, w1 = tig + 4 + 8 * ks;
            uint32_t ah[2][4], al[2][4];
#pragma unroll
            for (int mt = 0; mt < 2; mt++) {
                int r = wid * 32 + mt * 16 + g;
                ah[mt][0] = ash[r][w0];  ah[mt][1] = ash[r + 8][w0];
                ah[mt][2] = ash[r][w1];  ah[mt][3] = ash[r + 8][w1];
                al[mt][0] = asl[r][w0];  al[mt][1] = asl[r + 8][w0];
                al[mt][2] = asl[r][w1];  al[mt][3] = asl[r + 8][w1];
            }
#pragma unroll
            for (int nt = 0; nt < 8; nt++) {
                int n = nt * 8 + g;
                uint32_t bh0 = bsh[n][w0], bh1 = bsh[n][w1];
                uint32_t bl0 = bsl[n][w0], bl1 = bsl[n][w1];
#pragma unroll
                for (int mt = 0; mt < 2; mt++) {
                    mma_bf16(acc[mt][nt], ah[mt], bh0, bh1);
                    mma_bf16(acc[mt][nt], ah[mt], bl0, bl1);
                    mma_bf16(acc[mt][nt], al[mt], bh0, bh1);
                }
            }
        }
    }
#pragma unroll
    for (int mt = 0; mt < 2; mt++) {
        int r0g = rowBase + wid * 32 + mt * 16 + g;
#pragma unroll
        for (int nt = 0; nt < 8; nt++) {
            int col = nt * 8 + tig * 2;
            if (r0g < M)
                *(float2*)(g_h + (size_t)r0g * 64 + col) =
                    make_float2(acc[mt][nt][0], acc[mt][nt][1]);
            if (r0g + 8 < M)
                *(float2*)(g_h + (size_t)(r0g + 8) * 64 + col) =
                    make_float2(acc[mt][nt][2], acc[mt][nt][3]);
        }
    }
}

// ---------------- fused agg1 + gemm2: g_h2 = relu(A g_h + b1) @ W2 -----------
// 256 threads (8 warps). Block tile = 128 nodes. Agg phase: warp w aggregates
// nodes [rowBase+16w, rowBase+16w+16), writes bf16 hi/lo words straight into
// the gemm A-tile SMEM (word index == lane == col/2). Gemm phase: warp w does
// rows 16w..16w+15 x 64 cols, K=64 in 2 chunks (B chunk reloaded per chunk).
__global__ void __launch_bounds__(256) fused_ag_kernel(const float* __restrict__ b1) {
    __shared__ uint32_t ash[128][36];   // A hi, K=64 -> 32 words (+4 pad)
    __shared__ uint32_t asl[128][36];   // A lo
    __shared__ uint32_t bsh[64][20];    // B hi, per-32k chunk
    __shared__ uint32_t bsl[64][20];    // B lo

    const float2* H = (const float2*)g_h;
    const int M = N_NODES;
    int t = threadIdx.x, wid = t >> 5, lane = t & 31;
    int g = lane >> 2, tig = lane & 3;
    int rowBase = blockIdx.x * 128;

    // ---- agg phase: 16 nodes per warp ----
    float2 bb = ((const float2*)b1)[lane];
#pragma unroll 1
    for (int i = 0; i < 16; i++) {
        int rl = wid * 16 + i;
        int node = rowBase + rl;
        uint32_t hw = 0, lw = 0;
        if (node < M) {
            float2 r = agg_node(H, node, lane);
            float ax = fmaxf(r.x + bb.x, 0.f);
            float ay = fmaxf(r.y + bb.y, 0.f);
            hw = split_pack(ax, ay, lw);
        }
        ash[rl][lane] = hw;
        asl[rl][lane] = lw;
    }

    // ---- gemm phase: K=64, 2 chunks of 32 ----
    float acc[8][4] = {};
#pragma unroll
    for (int ch = 0; ch < 2; ch++) {
        int k0 = ch * 32;
        __syncthreads();   // (ch0: agg writes visible; ch1: prev mma done)
        {   // load B chunk: 64 n x 16 words, hi+lo (256 threads -> 1 uint4 each)
            int n = t >> 2, u = t & 3;
            *(uint4*)&bsh[n][u * 4] = *(const uint4*)(g_b2hi + (size_t)n * 64 + k0 + u * 8);
            *(uint4*)&bsl[n][u * 4] = *(const uint4*)(g_b2lo + (size_t)n * 64 + k0 + u * 8);
        }
        __syncthreads();

#pragma unroll
        for (int ks = 0; ks < 2; ks++) {
            int wa0 = ch * 16 + ks * 8 + tig, wa1 = wa0 + 4;   // A word idx (global k)
            int wb0 = ks * 8 + tig, wb1 = wb0 + 4;             // B word idx (chunk)
            int r = wid * 16 + g;
            uint32_t ah[4], al[4];
            ah[0] = ash[r][wa0];  ah[1] = ash[r + 8][wa0];
            ah[2] = ash[r][wa1];  ah[3] = ash[r + 8][wa1];
            al[0] = asl[r][wa0];  al[1] = asl[r + 8][wa0];
            al[2] = asl[r][wa1];  al[3] = asl[r + 8][wa1];
#pragma unroll
            for (int nt = 0; nt < 8; nt++) {
                int n = nt * 8 + g;
                uint32_t bh0 = bsh[n][wb0], bh1 = bsh[n][wb1];
                uint32_t bl0 = bsl[n][wb0], bl1 = bsl[n][wb1];
                mma_bf16(acc[nt], ah, bh0, bh1);
                mma_bf16(acc[nt], ah, bl0, bl1);
                mma_bf16(acc[nt], al, bh0, bh1);
            }
        }
    }
    // epilogue -> g_h2
    int r0g = rowBase + wid * 16 + g;
#pragma unroll
    for (int nt = 0; nt < 8; nt++) {
        int col = nt * 8 + tig * 2;
        if (r0g < M)
            *(float2*)(g_h2 + (size_t)r0g * 64 + col) = make_float2(acc[nt][0], acc[nt][1]);
        if (r0g + 8 < M)
            *(float2*)(g_h2 + (size_t)(r0g + 8) * 64 + col) = make_float2(acc[nt][2], acc[nt][3]);
    }
}

// ---------------- agg2: out = A g_h2 + b2 ------------------------------------
__global__ void __launch_bounds__(256) agg2_kernel(
    const float* __restrict__ bias, float2* __restrict__ outp) {
    const float2* H = (const float2*)g_h2;
    int gw   = (blockIdx.x * blockDim.x + threadIdx.x) >> 5;
    int lane = threadIdx.x & 31;
    if (gw >= N_NODES) return;
    float2 r = agg_node(H, gw, lane);
    float2 bb = ((const float2*)bias)[lane];
    outp[(size_t)gw * 32 + lane] = make_float2(r.x + bb.x, r.y + bb.y);
}

// ---------------- launch -----------------------------------------------------
extern "C" void kernel_launch(void* const* d_in, const int* in_sizes, int n_in,
                              void* d_out, int out_size) {
    const float* x   = (const float*)d_in[0];
    const void*  ei  = d_in[1];
    const float* ew  = (const float*)d_in[2];
    const float* W1  = (const float*)d_in[3];
    const float* b1  = (const float*)d_in[4];
    const float* W2  = (const float*)d_in[5];
    const float* b2  = (const float*)d_in[6];
    float*       out = (float*)d_out;

    const int TPB = 256;
    int nBlocksN = (N_NODES + TPB - 1) / TPB;
    int nBlocksE = (N_EDGES + TPB - 1) / TPB;
    int tileBlocks = (N_NODES + 127) / 128;   // 782
    int aggBlocks  = (N_NODES + 7) / 8;       // 12500

    // CSR build
    init_kernel<<<nBlocksN, TPB>>>((const int*)ei, W1, W2);
    deg_hist_kernel<<<nBlocksE, TPB>>>(ei, ew);
    scan1_kernel<<<NSB, 1024>>>();
    scan2_kernel<<<1, 128>>>();
    scan3_kernel<<<NSB, 1024>>>();
    reorder_kernel<<<nBlocksE, TPB>>>(ei, ew);

    // layer 1 transform
    gemm1_kernel<<<tileBlocks, 128>>>(x);
    // layer 1 propagate + layer 2 transform (fused)
    fused_ag_kernel<<<tileBlocks, 256>>>(b1);
    // layer 2 propagate
    agg2_kernel<<<aggBlocks, TPB>>>(b2, (float2*)out);
}

// round 10
// speedup vs baseline: 1.1917x; 1.1512x over previous
#include <cuda_runtime.h>
#include <cuda_bf16.h>
#include <cstdint>
#include <cstring>

#define N_NODES 100000
#define N_EDGES 1600000
#define IN_DIM  512
#define HID_DIM 64
#define NSB ((N_NODES + 1023) / 1024)   // 98 scan blocks

typedef unsigned long long u64;
#define DC_ONE_CNT (((u64)1) << 48)
#define DC_SCALE   1099511627776.0f     // 2^40
#define DC_INV     (1.0f / 1099511627776.0f)
#define DC_MASK    0xFFFFFFFFFFFFULL

// ---------------- scratch (static device globals: allocation-free) ----------
__device__ int   g_idx64;
__device__ u64   g_dc[N_NODES];          // packed: cnt<<48 | fixed-point deg
__device__ float g_dinv[N_NODES];
__device__ int   g_rs[N_NODES + 1];
__device__ int   g_cur[N_NODES];
__device__ int   g_bsum[NSB];
__device__ int   g_boff[NSB];
__device__ int   g_src[N_EDGES];
__device__ float g_w[N_EDGES];
__device__ float g_h[(size_t)N_NODES * HID_DIM];   // GEMM output (both layers)
__device__ float g_h2[(size_t)N_NODES * HID_DIM];  // layer-1 agg output
// bf16 hi/lo split of W, stored [n][k] (B operand)
__device__ __nv_bfloat16 g_b1hi[64 * IN_DIM];
__device__ __nv_bfloat16 g_b1lo[64 * IN_DIM];
__device__ __nv_bfloat16 g_b2hi[64 * HID_DIM];
__device__ __nv_bfloat16 g_b2lo[64 * HID_DIM];

// ---------------- helpers -----------------------------------------------------
__device__ __forceinline__ void mma_bf16(float* c, const uint32_t* a,
                                         uint32_t b0, uint32_t b1) {
    asm("mma.sync.aligned.m16n8k16.row.col.f32.bf16.bf16.f32 "
        "{%0,%1,%2,%3},{%4,%5,%6,%7},{%8,%9},{%0,%1,%2,%3};"
        : "+f"(c[0]), "+f"(c[1]), "+f"(c[2]), "+f"(c[3])
        : "r"(a[0]), "r"(a[1]), "r"(a[2]), "r"(a[3]), "r"(b0), "r"(b1));
}
__device__ __forceinline__ int load_idx(const void* ei, long long pos) {
    if (g_idx64) return (int)((const long long*)ei)[pos];
    return ((const int*)ei)[pos];
}
__device__ __forceinline__ uint32_t bf2u(__nv_bfloat162 t) {
    uint32_t u; memcpy(&u, &t, 4); return u;
}

// ---------------- init: deg/cnt + dtype detect + W split ---------------------
__global__ void init_kernel(const int* __restrict__ ei32,
                            const float* __restrict__ W1,
                            const float* __restrict__ W2) {
    int i = blockIdx.x * blockDim.x + threadIdx.x;
    // self-loop: count 1, weight 1.0 (fixed-point 2^40)
    if (i < N_NODES) g_dc[i] = DC_ONE_CNT + (u64)(1.0f * DC_SCALE);
    if (blockIdx.x == 0 && threadIdx.x < 32) {
        int nz = 0;
#pragma unroll
        for (int j = 0; j < 4; j++) nz |= ei32[1 + 2 * (threadIdx.x * 4 + j)];
        unsigned b = __ballot_sync(0xffffffffu, nz != 0);
        if (threadIdx.x == 0) g_idx64 = (b == 0u) ? 1 : 0;
    }
    if (i < IN_DIM * 64) {
        int k = i / 64, n = i % 64;
        float w = W1[i];
        __nv_bfloat16 h = __float2bfloat16(w);
        g_b1hi[n * IN_DIM + k] = h;
        g_b1lo[n * IN_DIM + k] = __float2bfloat16(w - __bfloat162float(h));
    }
    if (i < HID_DIM * 64) {
        int k = i / 64, n = i % 64;
        float w = W2[i];
        __nv_bfloat16 h = __float2bfloat16(w);
        g_b2hi[n * HID_DIM + k] = h;
        g_b2lo[n * HID_DIM + k] = __float2bfloat16(w - __bfloat162float(h));
    }
}

// one packed 64-bit atomic per edge
__global__ void deg_hist_kernel(const void* __restrict__ ei,
                                const float* __restrict__ ew) {
    int e = blockIdx.x * blockDim.x + threadIdx.x;
    if (e >= N_EDGES) return;
    int d = load_idx(ei, (long long)N_EDGES + e);
    if ((unsigned)d < (unsigned)N_NODES) {
        u64 p = DC_ONE_CNT + (u64)(ew[e] * DC_SCALE);
        atomicAdd(&g_dc[d], p);
    }
}

// ---------------- scans (decode packed deg/cnt in scan1) ---------------------
__global__ void scan1_kernel() {
    __shared__ int ws[32];
    int b = blockIdx.x, tid = threadIdx.x, lane = tid & 31, wid = tid >> 5;
    int i = b * 1024 + tid;
    u64 p = (i < N_NODES) ? g_dc[i] : 0ULL;
    if (i < N_NODES) {
        float deg = (float)(p & DC_MASK) * DC_INV;
        g_dinv[i] = (deg > 0.0f) ? rsqrtf(deg) : 0.0f;
    }
    int v = (int)(p >> 48);
    int x = v;
#pragma unroll
    for (int off = 1; off < 32; off <<= 1) {
        int y = __shfl_up_sync(0xffffffffu, x, off);
        if (lane >= off) x += y;
    }
    if (lane == 31) ws[wid] = x;
    __syncthreads();
    if (wid == 0) {
        int s = ws[lane];
#pragma unroll
        for (int off = 1; off < 32; off <<= 1) {
            int y = __shfl_up_sync(0xffffffffu, s, off);
            if (lane >= off) s += y;
        }
        ws[lane] = s;
    }
    __syncthreads();
    int incl = x + (wid > 0 ? ws[wid - 1] : 0);
    if (i < N_NODES) g_rs[i] = incl - v;   // block-local exclusive (self-loop excluded from edge list: cnt includes it? no — cnt counts only real edges plus... see note below)
    if (tid == 1023) g_bsum[b] = incl;
}

__global__ void scan2_kernel() {
    __shared__ int ws[4];
    int tid = threadIdx.x, lane = tid & 31, wid = tid >> 5;
    int v = (tid < NSB) ? g_bsum[tid] : 0;
    int x = v;
#pragma unroll
    for (int off = 1; off < 32; off <<= 1) {
        int y = __shfl_up_sync(0xffffffffu, x, off);
        if (lane >= off) x += y;
    }
    if (lane == 31) ws[wid] = x;
    __syncthreads();
    if (tid == 0) {
        int a = 0;
        for (int j = 0; j < 4; j++) { int t = ws[j]; ws[j] = a; a += t; }
    }
    __syncthreads();
    int excl = x - v + ws[wid];
    if (tid < NSB) g_boff[tid] = excl;
    if (tid == NSB - 1) g_rs[N_NODES] = excl + v;
}

__global__ void scan3_kernel() {
    int i = blockIdx.x * 1024 + threadIdx.x;
    if (i < N_NODES) {
        int r = g_rs[i] + g_boff[blockIdx.x];
        g_rs[i] = r;
        g_cur[i] = r;
    }
}

__global__ void reorder_kernel(const void* __restrict__ ei,
                               const float* __restrict__ ew) {
    int e = blockIdx.x * blockDim.x + threadIdx.x;
    if (e >= N_EDGES) return;
    int s = load_idx(ei, e);
    int d = load_idx(ei, (long long)N_EDGES + e);
    if ((unsigned)d >= (unsigned)N_NODES) return;
    int p = atomicAdd(&g_cur[d], 1);
    if ((unsigned)s < (unsigned)N_NODES) {
        g_src[p] = s;
        g_w[p]   = g_dinv[s] * ew[e] * g_dinv[d];
    } else {
        g_src[p] = 0;
        g_w[p]   = 0.0f;
    }
}

// NOTE on scan1: g_dc count includes the self-loop (+1), so g_rs allocates one
// extra slot per node beyond real edges. Those slots are never written by
// reorder; they must contribute zero. We zero-fill g_w slack below in reorder's
// companion (slack_kernel) to keep agg sums exact.
__global__ void slack_kernel() {
    // zero the one never-written slot per node: position g_cur_final..rs[i+1]-1
    // Simpler: since count included self-loop, there is exactly 1 slack slot per
    // node at the END of its segment IF all its edges were valid. Zero by index:
    int node = blockIdx.x * blockDim.x + threadIdx.x;
    if (node >= N_NODES) return;
    int e = g_rs[node + 1] - 1;       // last slot of node's segment
    g_src[e] = 0;
    g_w[e] = 0.0f;                    // overwritten later by reorder? no: reorder ran first; this runs AFTER? see launch order
}

// ---------------- GEMM: g_h[M,64] = X[M,K] @ W[K,64], bf16 3-pass -----------
// truncation hi/lo split of A: hi = bits&0xFFFF0000 (exact), lo = x - hi.
template <int K, bool FROM_G_H2>
__global__ void __launch_bounds__(128) mma_gemm_kernel(
    const float* __restrict__ Xext) {
    __shared__ uint32_t ash[128][20];
    __shared__ uint32_t asl[128][20];
    __shared__ uint32_t bsh[64][20];
    __shared__ uint32_t bsl[64][20];

    const float* X = FROM_G_H2 ? (const float*)g_h2 : Xext;
    const __nv_bfloat16* Bhi = (K == IN_DIM) ? g_b1hi : g_b2hi;
    const __nv_bfloat16* Blo = (K == IN_DIM) ? g_b1lo : g_b2lo;

    const int M = N_NODES;
    int t = threadIdx.x, wid = t >> 5, lane = t & 31;
    int g = lane >> 2, tig = lane & 3;
    int rowBase = blockIdx.x * 128;

    float acc[2][8][4] = {};

    for (int ch = 0; ch < K / 32; ch++) {
        int k0 = ch * 32;
        __syncthreads();
#pragma unroll
        for (int it = 0; it < 8; it++) {
            int id = t + it * 128;
            int row = id >> 3, q = id & 7;
            int gr = rowBase + row;
            float4 v = make_float4(0.f, 0.f, 0.f, 0.f);
            if (gr < M) v = *(const float4*)(X + (size_t)gr * K + k0 + q * 4);
            uint32_t xb = __float_as_uint(v.x), yb = __float_as_uint(v.y);
            uint32_t zb = __float_as_uint(v.z), wb = __float_as_uint(v.w);
            uint32_t h0 = __byte_perm(xb, yb, 0x7632);   // {y_hi, x_hi}
            uint32_t h1 = __byte_perm(zb, wb, 0x7632);
            float lx = v.x - __uint_as_float(xb & 0xFFFF0000u);
            float ly = v.y - __uint_as_float(yb & 0xFFFF0000u);
            float lz = v.z - __uint_as_float(zb & 0xFFFF0000u);
            float lw = v.w - __uint_as_float(wb & 0xFFFF0000u);
            uint32_t l0 = bf2u(__floats2bfloat162_rn(lx, ly));
            uint32_t l1 = bf2u(__floats2bfloat162_rn(lz, lw));
            ash[row][q * 2] = h0; ash[row][q * 2 + 1] = h1;
            asl[row][q * 2] = l0; asl[row][q * 2 + 1] = l1;
        }
#pragma unroll
        for (int it = 0; it < 2; it++) {
            int id = t + it * 128;
            int n = id >> 2, u = id & 3;
            *(uint4*)&bsh[n][u * 4] = *(const uint4*)(Bhi + (size_t)n * K + k0 + u * 8);
            *(uint4*)&bsl[n][u * 4] = *(const uint4*)(Blo + (size_t)n * K + k0 + u * 8);
        }
        __syncthreads();

#pragma unroll
        for (int ks = 0; ks < 2; ks++) {
            int w0 = tig + 8 * ks, w1 = tig + 4 + 8 * ks;
            uint32_t ah[2][4], al[2][4];
#pragma unroll
            for (int mt = 0; mt < 2; mt++) {
                int r = wid * 32 + mt * 16 + g;
                ah[mt][0] = ash[r][w0];  ah[mt][1] = ash[r + 8][w0];
                ah[mt][2] = ash[r][w1];  ah[mt][3] = ash[r + 8][w1];
                al[mt][0] = asl[r][w0];  al[mt][1] = asl[r + 8][w0];
                al[mt][2] = asl[r][w1];  al[mt][3] = asl[r + 8][w1];
            }
#pragma unroll
            for (int nt = 0; nt < 8; nt++) {
                int n = nt * 8 + g;
                uint32_t bh0 = bsh[n][w0], bh1 = bsh[n][w1];
                uint32_t bl0 = bsl[n][w0], bl1 = bsl[n][w1];
#pragma unroll
                for (int mt = 0; mt < 2; mt++) {
                    mma_bf16(acc[mt][nt], ah[mt], bh0, bh1);
                    mma_bf16(acc[mt][nt], ah[mt], bl0, bl1);
                    mma_bf16(acc[mt][nt], al[mt], bh0, bh1);
                }
            }
        }
    }
#pragma unroll
    for (int mt = 0; mt < 2; mt++) {
        int r0g = rowBase + wid * 32 + mt * 16 + g;
#pragma unroll
        for (int nt = 0; nt < 8; nt++) {
            int col = nt * 8 + tig * 2;
            if (r0g < M)
                *(float2*)(g_h + (size_t)r0g * 64 + col) =
                    make_float2(acc[mt][nt][0], acc[mt][nt][1]);
            if (r0g + 8 < M)
                *(float2*)(g_h + (size_t)(r0g + 8) * 64 + col) =
                    make_float2(acc[mt][nt][2], acc[mt][nt][3]);
        }
    }
}

// ---------------- aggregation: warp per node, CSR gather, no atomics --------
template <bool RELU>
__global__ void __launch_bounds__(256) agg_kernel(
    const float* __restrict__ bias, float2* __restrict__ outp) {
    const float2* H = (const float2*)g_h;
    float2* out = RELU ? (float2*)g_h2 : outp;

    int gw   = (blockIdx.x * blockDim.x + threadIdx.x) >> 5;
    int lane = threadIdx.x & 31;
    if (gw >= N_NODES) return;
    int node = gw;

    float di = g_dinv[node];
    float sn = di * di;
    float2 hv = H[(size_t)node * 32 + lane];
    float ax = sn * hv.x, ay = sn * hv.y;

    int b = g_rs[node], en = g_rs[node + 1];
    for (int i = b; i < en; i += 32) {
        int rem = en - i;
        int src = 0; float w = 0.f;
        if (lane < rem) { src = g_src[i + lane]; w = g_w[i + lane]; }
        int m = rem < 32 ? rem : 32;
        int j = 0;
        for (; j + 4 <= m; j += 4) {
            int   s0 = __shfl_sync(0xffffffffu, src, j);
            int   s1 = __shfl_sync(0xffffffffu, src, j + 1);
            int   s2 = __shfl_sync(0xffffffffu, src, j + 2);
            int   s3 = __shfl_sync(0xffffffffu, src, j + 3);
            float w0 = __shfl_sync(0xffffffffu, w, j);
            float w1 = __shfl_sync(0xffffffffu, w, j + 1);
            float w2 = __shfl_sync(0xffffffffu, w, j + 2);
            float w3 = __shfl_sync(0xffffffffu, w, j + 3);
            float2 x0 = H[(size_t)s0 * 32 + lane];
            float2 x1 = H[(size_t)s1 * 32 + lane];
            float2 x2 = H[(size_t)s2 * 32 + lane];
            float2 x3 = H[(size_t)s3 * 32 + lane];
            ax += w0 * x0.x; ay += w0 * x0.y;
            ax += w1 * x1.x; ay += w1 * x1.y;
            ax += w2 * x2.x; ay += w2 * x2.y;
            ax += w3 * x3.x; ay += w3 * x3.y;
        }
        for (; j < m; j++) {
            int   s0 = __shfl_sync(0xffffffffu, src, j);
            float w0 = __shfl_sync(0xffffffffu, w, j);
            float2 x0 = H[(size_t)s0 * 32 + lane];
            ax += w0 * x0.x; ay += w0 * x0.y;
        }
    }
    float2 bb = ((const float2*)bias)[lane];
    ax += bb.x; ay += bb.y;
    if (RELU) { ax = fmaxf(ax, 0.f); ay = fmaxf(ay, 0.f); }
    out[(size_t)node * 32 + lane] = make_float2(ax, ay);
}

// ---------------- launch -----------------------------------------------------
extern "C" void kernel_launch(void* const* d_in, const int* in_sizes, int n_in,
                              void* d_out, int out_size) {
    const float* x   = (const float*)d_in[0];
    const void*  ei  = d_in[1];
    const float* ew  = (const float*)d_in[2];
    const float* W1  = (const float*)d_in[3];
    const float* b1  = (const float*)d_in[4];
    const float* W2  = (const float*)d_in[5];
    const float* b2  = (const float*)d_in[6];
    float*       out = (float*)d_out;

    const int TPB = 256;
    int nBlocksN = (N_NODES + TPB - 1) / TPB;
    int nBlocksE = (N_EDGES + TPB - 1) / TPB;
    int gemmBlocks = (N_NODES + 127) / 128;
    int aggBlocks  = (N_NODES + 7) / 8;

    // CSR build. Count in g_dc includes the self-loop, so each node's segment
    // has exactly one extra slot; slack_kernel zeroes it BEFORE reorder fills
    // real edges (reorder only fills the first cnt-1... actually fills exactly
    // the real-edge count; the final slot of each segment stays as slack).
    init_kernel<<<nBlocksN, TPB>>>((const int*)ei, W1, W2);
    deg_hist_kernel<<<nBlocksE, TPB>>>(ei, ew);
    scan1_kernel<<<NSB, 1024>>>();
    scan2_kernel<<<1, 128>>>();
    scan3_kernel<<<NSB, 1024>>>();
    slack_kernel<<<nBlocksN, TPB>>>();       // zero the per-node slack slot
    reorder_kernel<<<nBlocksE, TPB>>>(ei, ew);

    // layer 1
    mma_gemm_kernel<IN_DIM, false><<<gemmBlocks, 128>>>(x);
    agg_kernel<true><<<aggBlocks, TPB>>>(b1, nullptr);

    // layer 2
    mma_gemm_kernel<HID_DIM, true><<<gemmBlocks, 128>>>(nullptr);
    agg_kernel<false><<<aggBlocks, TPB>>>(b2, (float2*)out);
}